// round 3
// baseline (speedup 1.0000x reference)
#include <cuda_runtime.h>
#include <math_constants.h>

// VerticalLinePool: out[b,c,h,w] = max_{h' >= h} x[b,c,h',w]
// x shape (8, 128, 256, 256) fp32, NCHW contiguous.
// One thread per (b,c, w/4) float4-column; scan h bottom-up with running max.
// Round 3: software-pipelined double-buffered batches — issue next batch's
// 8 LDG.E.128 before consuming the current batch, so load injection into the
// memory system is continuous instead of bursty.

#define H_DIM 256
#define W4    64                 // W / 4 float4s per row
#define NITEMS (8 * 128 * W4)    // 65536 float4-columns
#define UB    8                  // batch size (loads in flight per buffer)
#define NBATCH (H_DIM / UB)      // 32 batches

__device__ __forceinline__ void load_batch(const float4* __restrict__ xp,
                                           int htop, float4 v[UB])
{
    #pragma unroll
    for (int i = 0; i < UB; ++i)
        v[i] = __ldcs(&xp[(size_t)(htop - i) * W4]);
}

__device__ __forceinline__ void consume_batch(float4* __restrict__ op,
                                              int htop, const float4 v[UB],
                                              float4& m)
{
    #pragma unroll
    for (int i = 0; i < UB; ++i) {
        m.x = fmaxf(m.x, v[i].x);
        m.y = fmaxf(m.y, v[i].y);
        m.z = fmaxf(m.z, v[i].z);
        m.w = fmaxf(m.w, v[i].w);
        __stcs(&op[(size_t)(htop - i) * W4], m);
    }
}

__global__ __launch_bounds__(64) void vertical_line_pool_kernel(
    const float4* __restrict__ x, float4* __restrict__ out)
{
    unsigned int t = blockIdx.x * 64u + threadIdx.x;   // 0 .. NITEMS-1
    unsigned int bc = t >> 6;          // (b,c) plane
    unsigned int w4 = t & 63u;         // float4 within a row

    size_t base = (size_t)bc * (H_DIM * W4) + w4;
    const float4* __restrict__ xp = x + base;
    float4* __restrict__ op = out + base;

    float4 m = make_float4(-CUDART_INF_F, -CUDART_INF_F, -CUDART_INF_F, -CUDART_INF_F);

    // Batch b covers h = (255 - 8b) down to (248 - 8b). Scan b = 0..31.
    float4 v[UB], w[UB];

    // Prologue: load batch 0.
    load_batch(xp, H_DIM - 1, v);

    // Steady state: 2x-unrolled ping-pong. Handles batches 0..30 consumed,
    // batch 31 loaded+consumed in epilogue.
    #pragma unroll 1
    for (int k = 0; k < (NBATCH - 2) / 2; ++k) {     // k = 0..14
        int b0 = 2 * k;
        load_batch(xp, H_DIM - 1 - (b0 + 1) * UB, w);    // load B(2k+1)
        consume_batch(op, H_DIM - 1 - b0 * UB, v, m);    // consume B(2k)
        load_batch(xp, H_DIM - 1 - (b0 + 2) * UB, v);    // load B(2k+2)
        consume_batch(op, H_DIM - 1 - (b0 + 1) * UB, w, m); // consume B(2k+1)
    }
    // After loop: batch 30 resident in v, batch 31 not yet loaded.
    load_batch(xp, H_DIM - 1 - 31 * UB, w);          // load B31
    consume_batch(op, H_DIM - 1 - 30 * UB, v, m);    // consume B30
    consume_batch(op, H_DIM - 1 - 31 * UB, w, m);    // consume B31
}

extern "C" void kernel_launch(void* const* d_in, const int* in_sizes, int n_in,
                              void* d_out, int out_size)
{
    const float4* x = (const float4*)d_in[0];
    float4* out = (float4*)d_out;

    dim3 grid(NITEMS / 64);   // 1024 blocks -> ~6.9/SM, single wave
    dim3 block(64);
    vertical_line_pool_kernel<<<grid, block>>>(x, out);
}

// round 4
// speedup vs baseline: 1.0052x; 1.0052x over previous
#include <cuda_runtime.h>
#include <math_constants.h>

// VerticalLinePool: out[b,c,h,w] = max_{h' >= h} x[b,c,h',w]
// x shape (8, 128, 256, 256) fp32, NCHW contiguous.
// Round 4: one thread per float2-column (2 adjacent w) -> 2x thread count vs
// float4 version: 2048 blocks, ~27.6 warps/SM (occ ~43%). More independent
// warps per SM = smoother read/write interleave at the HBM controllers.

#define H_DIM 256
#define W2    128                // W / 2 float2s per row
#define NITEMS (8 * 128 * W2)    // 131072 float2-columns
#define UB    8

__global__ __launch_bounds__(64) void vertical_line_pool_kernel(
    const float2* __restrict__ x, float2* __restrict__ out)
{
    unsigned int t = blockIdx.x * 64u + threadIdx.x;   // 0 .. NITEMS-1
    unsigned int bc = t >> 7;           // (b,c) plane
    unsigned int w2 = t & 127u;         // float2 within a row

    size_t base = (size_t)bc * (H_DIM * W2) + w2;
    const float2* __restrict__ xp = x + base;
    float2* __restrict__ op = out + base;

    float2 m = make_float2(-CUDART_INF_F, -CUDART_INF_F);

    // Scan from bottom (h = 255) to top (h = 0) in batches of 8 independent
    // LDG.64, then fmax chain + 8 STG.64.
    for (int h0 = H_DIM - 1; h0 >= 0; h0 -= UB) {
        float2 v[UB];
        #pragma unroll
        for (int i = 0; i < UB; ++i)
            v[i] = __ldcs(&xp[(size_t)(h0 - i) * W2]);
        #pragma unroll
        for (int i = 0; i < UB; ++i) {
            m.x = fmaxf(m.x, v[i].x);
            m.y = fmaxf(m.y, v[i].y);
            __stcs(&op[(size_t)(h0 - i) * W2], m);
        }
    }
}

extern "C" void kernel_launch(void* const* d_in, const int* in_sizes, int n_in,
                              void* d_out, int out_size)
{
    const float2* x = (const float2*)d_in[0];
    float2* out = (float2*)d_out;

    dim3 grid(NITEMS / 64);   // 2048 blocks -> ~13.8/SM, single wave
    dim3 block(64);
    vertical_line_pool_kernel<<<grid, block>>>(x, out);
}